// round 16
// baseline (speedup 1.0000x reference)
#include <cuda_runtime.h>
#include <cuda_fp16.h>
#include <cstdint>
#include <math.h>

// ---------------- problem constants ----------------
#define CC        256
#define LQQ       5376
#define BTT       4
#define NLAYERS   6
#define NPIX      16384
#define ROWS_TOK  (BTT*LQQ)     // 21504
#define ROWS_PIX  (BTT*NPIX)    // 65536
#define NTILES    16384         // BTT * 64 * 64 winograd tiles
#define ZPL       (NTILES*256)  // elements per winograd z-plane

// ---------------- scratch (device globals) ----------------
__device__ float  g_posf[ROWS_TOK*CC];
__device__ float  g_oa  [ROWS_TOK*384];
__device__ float  g_tmp [ROWS_TOK*CC];
__device__ float  g_osnap[ROWS_TOK*CC];
__device__ float  g_mtok[(long long)ROWS_PIX*CC];
__device__ __half g_outh[ROWS_TOK*CC];
__device__ __half g_qh  [ROWS_TOK*CC];
__device__ __half g_vh  [ROWS_TOK*CC];
__device__ __half g_acch[ROWS_TOK*CC];
__device__ __half g_ffh [ROWS_TOK*1024];
__device__ __half g_xh  [(long long)ROWS_PIX*CC];
__device__ __half g_mh  [(long long)ROWS_PIX*CC];
__device__ __half g_valT[NLAYERS*65536];
__device__ __half g_oaT [NLAYERS*98304];
__device__ __half g_outT[NLAYERS*65536];
__device__ __half g_ff1T[NLAYERS*262144];
__device__ __half g_ff2T[NLAYERS*262144];
__device__ __half g_latT[NLAYERS*65536];
__device__ float  g_oab [NLAYERS*384];
__device__ __half g_U   [(long long)NLAYERS*16*65536];
__device__ __half g_V   [(long long)16*ZPL];
__device__ __half g_M   [(long long)16*ZPL];
__device__ float  g_zerob[256];

// ---------------- helpers ----------------
__device__ __forceinline__ void mma_f16(float* d, const uint32_t* a, const uint32_t* b){
    asm volatile("mma.sync.aligned.m16n8k16.row.col.f32.f16.f16.f32 "
        "{%0,%1,%2,%3}, {%4,%5,%6,%7}, {%8,%9}, {%0,%1,%2,%3};"
        : "+f"(d[0]), "+f"(d[1]), "+f"(d[2]), "+f"(d[3])
        : "r"(a[0]), "r"(a[1]), "r"(a[2]), "r"(a[3]), "r"(b[0]), "r"(b[1]));
}
__device__ __forceinline__ void ldsm4(uint32_t* r, uint32_t addr){
    asm volatile("ldmatrix.sync.aligned.m8n8.x4.shared.b16 {%0,%1,%2,%3}, [%4];"
        : "=r"(r[0]), "=r"(r[1]), "=r"(r[2]), "=r"(r[3]) : "r"(addr));
}
__device__ __forceinline__ uint32_t smem_u32(const void* p){
    uint32_t a; asm("{ .reg .u64 t; cvta.to.shared.u64 t, %1; cvt.u32.u64 %0, t; }" : "=r"(a) : "l"(p)); return a;
}
__device__ __forceinline__ void cpa16(uint32_t dst, const void* src){
    asm volatile("cp.async.cg.shared.global [%0], [%1], 16;\n" :: "r"(dst), "l"(src) : "memory");
}
#define CPA_COMMIT() asm volatile("cp.async.commit_group;" ::: "memory")
#define CPA_WAIT(n)  asm volatile("cp.async.wait_group %0;" :: "n"(n) : "memory")

// ---------------- fp16 mma GEMM: BM=BN=128, BK=32, NSTG=4, single-sync, z-batched ----
// EPI 0: float C = acc+bias ; EPI 1: half C = relu(acc+bias) ; EPI 2: half C = acc+bias
#define LDH  40
#define STH  (128*LDH)
#define NSTG 4
#define SMEM_MMA (NSTG*2*STH*2)         // 81920 bytes

__device__ __forceinline__ void issue_tile(
    const __half* __restrict__ A, const __half* __restrict__ B,
    uint32_t smA, uint32_t smB, int kc, long long m0, int n0, int lda, int ldbK, int tid)
{
    const int row = tid >> 1;
    const int s0  = (tid & 1) * 2;
#pragma unroll
    for (int j = 0; j < 2; j++) {
        const int slot = s0 + j;
        cpa16(smA + (uint32_t)(row * LDH + slot * 8) * 2u,
              A + (m0 + row) * (long long)lda + kc * 32 + slot * 8);
        cpa16(smB + (uint32_t)(row * LDH + slot * 8) * 2u,
              B + (long long)(n0 + row) * ldbK + kc * 32 + slot * 8);
    }
}

template<int EPI>
__global__ void __launch_bounds__(256, 2) k_mma(
    const __half* __restrict__ A, const __half* __restrict__ B,
    const float* __restrict__ bias, void* __restrict__ Cv,
    int K, int lda, int ldc,
    long long zsa, long long zsb, long long zsc)
{
    extern __shared__ __half smh[];
    const uint32_t smbase = smem_u32(smh);

    A += (long long)blockIdx.z * zsa;
    B += (long long)blockIdx.z * zsb;
    const long long czoff = (long long)blockIdx.z * zsc;

    const int tid  = threadIdx.x;
    const int lane = tid & 31;
    const int wid  = tid >> 5;
    const int wm   = wid >> 1;
    const int wn   = wid & 1;
    const int gq   = lane >> 2;
    const int tg   = lane & 3;
    const long long m0 = (long long)blockIdx.y * 128;
    const int n0 = blockIdx.x * 128;
    const int NC = K >> 5;

    const int aoff = (wm * 32 + (lane & 7) + (lane & 8)) * LDH + ((lane & 16) >> 1);
    const int boff = (wn * 64 + (lane & 7) + ((lane & 16) >> 1)) * LDH + (lane & 8);

#pragma unroll
    for (int s = 0; s < NSTG - 1; s++) {
        if (s < NC) {
            issue_tile(A, B, smbase + (uint32_t)(s*2*STH)*2u,
                       smbase + (uint32_t)((s*2+1)*STH)*2u, s, m0, n0, lda, K, tid);
            CPA_COMMIT();
        }
    }

    float acc[2][8][4];
#pragma unroll
    for (int i = 0; i < 2; i++)
#pragma unroll
        for (int j = 0; j < 8; j++)
#pragma unroll
            for (int t = 0; t < 4; t++) acc[i][j][t] = 0.f;

    for (int kc = 0; kc < NC; kc++) {
        const int rem = NC - 1 - kc;
        if (rem >= 2)      CPA_WAIT(2);
        else if (rem == 1) CPA_WAIT(1);
        else               CPA_WAIT(0);
        __syncthreads();

        const int nt = kc + NSTG - 1;
        if (nt < NC) {
            const int wst = nt % NSTG;
            issue_tile(A, B, smbase + (uint32_t)(wst*2*STH)*2u,
                       smbase + (uint32_t)((wst*2+1)*STH)*2u, nt, m0, n0, lda, K, tid);
            CPA_COMMIT();
        }

        const int st = kc % NSTG;
        const uint32_t stA = smbase + (uint32_t)(st * 2 * STH) * 2u;
        const uint32_t stB = stA + (uint32_t)STH * 2u;
#pragma unroll
        for (int ks = 0; ks < 2; ks++) {
            uint32_t afr[2][4], bfr[8][2];
#pragma unroll
            for (int im = 0; im < 2; im++)
                ldsm4(afr[im], stA + (uint32_t)(aoff + im * 16 * LDH + ks * 16) * 2u);
#pragma unroll
            for (int g = 0; g < 4; g++) {
                uint32_t t4[4];
                ldsm4(t4, stB + (uint32_t)(boff + g * 16 * LDH + ks * 16) * 2u);
                bfr[2*g][0] = t4[0]; bfr[2*g][1] = t4[1];
                bfr[2*g+1][0] = t4[2]; bfr[2*g+1][1] = t4[3];
            }
#pragma unroll
            for (int im = 0; im < 2; im++)
#pragma unroll
                for (int in_ = 0; in_ < 8; in_++)
                    mma_f16(acc[im][in_], afr[im], bfr[in_]);
        }
    }

    // ---- epilogue ----
    float* Cf = (float*)Cv;
    __half* Ch = (__half*)Cv;
#pragma unroll
    for (int im = 0; im < 2; im++) {
        const long long rbase = m0 + wm * 32 + im * 16 + gq;
#pragma unroll
        for (int half_ = 0; half_ < 2; half_++) {
            const long long r = rbase + half_ * 8;
#pragma unroll
            for (int in_ = 0; in_ < 8; in_++) {
                const int col = n0 + wn * 64 + in_ * 8 + tg * 2;
                float ox = acc[im][in_][half_ * 2 + 0] + bias[col];
                float oy = acc[im][in_][half_ * 2 + 1] + bias[col + 1];
                if (EPI == 1) { ox = fmaxf(ox, 0.f); oy = fmaxf(oy, 0.f); }
                const long long ci = r * (long long)ldc + col + czoff;
                if (EPI == 0) {
                    *(float2*)(Cf + ci) = make_float2(ox, oy);
                } else {
                    *(__half2*)(Ch + ci) = __floats2half2_rn(ox, oy);
                }
            }
        }
    }
}

// ---------------- winograd input transform + fused bilinear upsample -----------------
__global__ __launch_bounds__(256) void k_wint(const __half* __restrict__ xh,
    const float* __restrict__ osnap, __half* __restrict__ V)
{
    const int i = blockIdx.x * 256 + threadIdx.x;   // NTILES*256
    const int c    = i & 255;
    const int tile = i >> 8;
    const int tx = tile & 63, ty = (tile >> 6) & 63, bt = tile >> 12;
    const int h0 = 2 * ty - 1, w0 = 2 * tx - 1;
    const float* ub = osnap + ((long long)bt * LQQ + 1280) * 256 + c;

    float d[4][4];
#pragma unroll
    for (int r = 0; r < 4; r++) {
        const int h = h0 + r;
        const bool hok = (unsigned)h < 128u;
        float sy = fminf(fmaxf(h * 0.5f - 0.25f, 0.f), 63.f);
        int y0 = (int)sy, y1 = min(y0 + 1, 63);
        float fy = sy - y0;
#pragma unroll
        for (int s = 0; s < 4; s++) {
            const int w = w0 + s;
            if (hok && (unsigned)w < 128u) {
                float xv = __half2float(xh[((long long)((bt << 14) + (h << 7) + w)) * 256 + c]);
                float sx = fminf(fmaxf(w * 0.5f - 0.25f, 0.f), 63.f);
                int x0 = (int)sx, x1 = min(x0 + 1, 63);
                float fx = sx - x0;
                float up = ub[(y0 * 64 + x0) * 256] * (1.f - fx) * (1.f - fy)
                         + ub[(y0 * 64 + x1) * 256] * fx * (1.f - fy)
                         + ub[(y1 * 64 + x0) * 256] * (1.f - fx) * fy
                         + ub[(y1 * 64 + x1) * 256] * fx * fy;
                d[r][s] = xv + up;
            } else {
                d[r][s] = 0.f;
            }
        }
    }
    float t[4][4];
#pragma unroll
    for (int j = 0; j < 4; j++) {
        t[0][j] = d[0][j] - d[2][j];
        t[1][j] = d[1][j] + d[2][j];
        t[2][j] = d[2][j] - d[1][j];
        t[3][j] = d[1][j] - d[3][j];
    }
    const long long base = (long long)tile * 256 + c;
#pragma unroll
    for (int r = 0; r < 4; r++) {
        V[(long long)(r*4+0) * ZPL + base] = __float2half_rn(t[r][0] - t[r][2]);
        V[(long long)(r*4+1) * ZPL + base] = __float2half_rn(t[r][1] + t[r][2]);
        V[(long long)(r*4+2) * ZPL + base] = __float2half_rn(t[r][2] - t[r][1]);
        V[(long long)(r*4+3) * ZPL + base] = __float2half_rn(t[r][1] - t[r][3]);
    }
}

// ---------------- winograd output transform + bias + relu + mask accumulate ----------
__global__ __launch_bounds__(256) void k_wout(const __half* __restrict__ M,
    const float* __restrict__ bias, float* __restrict__ mtok, __half* __restrict__ mh)
{
    const int i = blockIdx.x * 256 + threadIdx.x;
    const int c    = i & 255;
    const int tile = i >> 8;
    const int tx = tile & 63, ty = (tile >> 6) & 63, bt = tile >> 12;

    float m[4][4];
    const long long base = (long long)tile * 256 + c;
#pragma unroll
    for (int z = 0; z < 16; z++)
        m[z >> 2][z & 3] = __half2float(M[(long long)z * ZPL + base]);

    float t[2][4];
#pragma unroll
    for (int j = 0; j < 4; j++) {
        t[0][j] = m[0][j] + m[1][j] + m[2][j];
        t[1][j] = m[1][j] - m[2][j] - m[3][j];
    }
    float y[2][2];
#pragma unroll
    for (int r = 0; r < 2; r++) {
        y[r][0] = t[r][0] + t[r][1] + t[r][2];
        y[r][1] = t[r][1] - t[r][2] - t[r][3];
    }
    const float bb = bias[c];
#pragma unroll
    for (int r = 0; r < 2; r++) {
#pragma unroll
        for (int s = 0; s < 2; s++) {
            const int py = 2 * ty + r, px = 2 * tx + s;
            const long long idx = ((long long)((bt << 14) + (py << 7) + px)) * 256 + c;
            float nv = mtok[idx] + fmaxf(y[r][s] + bb, 0.f);
            mtok[idx] = nv;
            mh[idx] = __float2half_rn(nv);
        }
    }
}

// ---------------- winograd weight transform ----------------
__global__ __launch_bounds__(256) void k_wu(const float* __restrict__ w, __half* __restrict__ U)
{
    const int i = blockIdx.x * 256 + threadIdx.x;   // NLAYERS*65536
    const int ic = i & 255;
    const int oc = (i >> 8) & 255;
    const int l  = i >> 16;
    const float* g = w + (((long long)l * 256 + oc) * 256 + ic) * 9;
    float Gg[4][3];
#pragma unroll
    for (int s = 0; s < 3; s++) {
        Gg[0][s] = g[s];
        Gg[1][s] = 0.5f * (g[s] + g[3 + s] + g[6 + s]);
        Gg[2][s] = 0.5f * (g[s] - g[3 + s] + g[6 + s]);
        Gg[3][s] = g[6 + s];
    }
#pragma unroll
    for (int r = 0; r < 4; r++) {
        const long long lb = ((long long)l * 16 + r * 4) * 65536 + oc * 256 + ic;
        U[lb]          = __float2half_rn(Gg[r][0]);
        U[lb + 65536]  = __float2half_rn(0.5f * (Gg[r][0] + Gg[r][1] + Gg[r][2]));
        U[lb + 131072] = __float2half_rn(0.5f * (Gg[r][0] - Gg[r][1] + Gg[r][2]));
        U[lb + 196608] = __float2half_rn(Gg[r][2]);
    }
}

// ---------------- token build ----------------
__global__ __launch_bounds__(256) void k_build(
    const float* __restrict__ s0, const float* __restrict__ s1, const float* __restrict__ s2,
    const float* __restrict__ p0, const float* __restrict__ p1, const float* __restrict__ p2,
    const float* __restrict__ lev, float* __restrict__ out, __half* __restrict__ outh,
    float* __restrict__ posf, __half* __restrict__ qh)
{
    long long i = (long long)blockIdx.x * 256 + threadIdx.x;
    int c = (int)(i & 255);
    long long r = i >> 8;
    int q  = (int)(r % LQQ);
    int bt = (int)(r / LQQ);
    int l, H, qq;
    if (q < 256)       { l = 0; H = 16; qq = q; }
    else if (q < 1280) { l = 1; H = 32; qq = q - 256; }
    else               { l = 2; H = 64; qq = q - 1280; }
    const float* s = (l == 0) ? s0 : (l == 1 ? s1 : s2);
    const float* p = (l == 0) ? p0 : (l == 1 ? p1 : p2);
    long long src = ((long long)(bt * CC + c)) * H * H + qq;
    float sv = s[src];
    float pv = p[src] + lev[l * CC + c];
    out[i]  = sv;
    outh[i] = __float2half_rn(sv);
    posf[i] = pv;
    qh[i]   = __float2half_rn(sv + pv);
}

// ---------------- deformable sampling ----------------
__global__ __launch_bounds__(256) void k_sample(
    const __half* __restrict__ v, const float* __restrict__ oa, __half* __restrict__ acc)
{
    int bq   = blockIdx.x;
    int h    = threadIdx.x >> 5;
    int lane = threadIdx.x & 31;
    int bt = bq / LQQ, q = bq % LQQ;

    int Hq, qq;
    if (q < 256)       { Hq = 16; qq = q; }
    else if (q < 1280) { Hq = 32; qq = q - 256; }
    else               { Hq = 64; qq = q - 1280; }
    float rx = ((qq % Hq) + 0.5f) / (float)Hq;
    float ry = ((qq / Hq) + 0.5f) / (float)Hq;

    const float* awp = oa + (long long)bq * 384 + 256 + h * 12;
    float a[12];
    float m = -1e30f;
#pragma unroll
    for (int j = 0; j < 12; j++) { a[j] = awp[j]; m = fmaxf(m, a[j]); }
    float s = 0.f;
#pragma unroll
    for (int j = 0; j < 12; j++) { a[j] = __expf(a[j] - m); s += a[j]; }
    float inv = 1.f / s;

    const float* offp = oa + (long long)bq * 384 + h * 24;
    float sum = 0.f;
    const int starts[3] = {0, 256, 1280};
    const int hs[3]     = {16, 32, 64};

#pragma unroll
    for (int l = 0; l < 3; l++) {
        int H = hs[l], W = hs[l];
        const __half* vl = v + ((long long)bt * LQQ + starts[l]) * CC + h * 32 + lane;
#pragma unroll
        for (int p = 0; p < 4; p++) {
            float ox = offp[(l * 4 + p) * 2 + 0];
            float oy = offp[(l * 4 + p) * 2 + 1];
            float x = rx * W + ox - 0.5f;
            float y = ry * H + oy - 0.5f;
            float x0f = floorf(x), y0f = floorf(y);
            int x0 = (int)x0f, y0 = (int)y0f;
            float fx = x - x0f, fy = y - y0f;
            float w00 = (1.f - fx) * (1.f - fy);
            float w01 = fx * (1.f - fy);
            float w10 = (1.f - fx) * fy;
            float w11 = fx * fy;
            float g = 0.f;
            if (y0 >= 0 && y0 < H) {
                if (x0 >= 0 && x0 < W)         g += w00 * __half2float(vl[(long long)(y0 * W + x0) * CC]);
                if (x0 + 1 >= 0 && x0 + 1 < W) g += w01 * __half2float(vl[(long long)(y0 * W + x0 + 1) * CC]);
            }
            if (y0 + 1 >= 0 && y0 + 1 < H) {
                if (x0 >= 0 && x0 < W)         g += w10 * __half2float(vl[(long long)((y0 + 1) * W + x0) * CC]);
                if (x0 + 1 >= 0 && x0 + 1 < W) g += w11 * __half2float(vl[(long long)((y0 + 1) * W + x0 + 1) * CC]);
            }
            sum += (a[l * 4 + p] * inv) * g;
        }
    }
    acc[(long long)bq * CC + h * 32 + lane] = __float2half_rn(sum);
}

// ---------------- layernorm ----------------
template<int QOUT>
__global__ __launch_bounds__(256) void k_ln(
    const float* __restrict__ res, const float* __restrict__ delta,
    const float* __restrict__ g, const float* __restrict__ b,
    float* __restrict__ out, __half* __restrict__ outh,
    const float* __restrict__ posf, __half* __restrict__ qh, float* __restrict__ osnap)
{
    int row = blockIdx.x, c = threadIdx.x;
    long long idx = (long long)row * CC + c;
    float x = res[idx] + delta[idx];
    float s1 = x, s2 = x * x;
#pragma unroll
    for (int o = 16; o; o >>= 1) {
        s1 += __shfl_xor_sync(0xffffffffu, s1, o);
        s2 += __shfl_xor_sync(0xffffffffu, s2, o);
    }
    __shared__ float a1[8], a2[8];
    int wid = c >> 5, ln = c & 31;
    if (ln == 0) { a1[wid] = s1; a2[wid] = s2; }
    __syncthreads();
    float S1 = 0.f, S2 = 0.f;
#pragma unroll
    for (int k = 0; k < 8; k++) { S1 += a1[k]; S2 += a2[k]; }
    float mean = S1 * (1.f / 256.f);
    float var  = S2 * (1.f / 256.f) - mean * mean;
    float r = rsqrtf(var + 1e-5f);
    float y = (x - mean) * r * g[c] + b[c];
    out[idx]  = y;
    outh[idx] = __float2half_rn(y);
    if (QOUT) {
        qh[idx] = __float2half_rn(y + posf[idx]);
        osnap[idx] = y;
    }
}

// ---------------- mask transposes ----------------
__global__ __launch_bounds__(256) void k_trpix0(const float* __restrict__ src,
                                                float* __restrict__ dst, __half* __restrict__ dsth)
{
    __shared__ float t[32][33];
    int tx = threadIdx.x & 31, ty = threadIdx.x >> 5;
    int p0 = blockIdx.x << 5;
    int c0 = blockIdx.y << 5;
    int bt = blockIdx.z;
    int b = bt >> 1, tt = bt & 1;
#pragma unroll
    for (int r = 0; r < 4; r++) {
        int c = c0 + ty + r * 8;
        t[ty + r * 8][tx] = src[(((long long)(b * CC + c)) * 2 + tt) * NPIX + p0 + tx];
    }
    __syncthreads();
#pragma unroll
    for (int r = 0; r < 4; r++) {
        int p = p0 + ty + r * 8;
        float v = t[tx][ty + r * 8];
        long long di = ((long long)bt * NPIX + p) * CC + c0 + tx;
        dst[di]  = v;
        dsth[di] = __float2half_rn(v);
    }
}

__global__ __launch_bounds__(256) void k_trpix1(const float* __restrict__ src, float* __restrict__ dst)
{
    __shared__ float t[32][33];
    int tx = threadIdx.x & 31, ty = threadIdx.x >> 5;
    int p0 = blockIdx.x << 5;
    int c0 = blockIdx.y << 5;
    int bt = blockIdx.z;
    int b = bt >> 1, tt = bt & 1;
#pragma unroll
    for (int r = 0; r < 4; r++) {
        int p = p0 + ty + r * 8;
        t[ty + r * 8][tx] = src[((long long)bt * NPIX + p) * CC + c0 + tx];
    }
    __syncthreads();
#pragma unroll
    for (int r = 0; r < 4; r++) {
        int c = c0 + ty + r * 8;
        dst[(((long long)(b * CC + c)) * 2 + tt) * NPIX + p0 + tx] = t[tx][ty + r * 8];
    }
}

// ---------------- fused weight prep ----------------
__global__ __launch_bounds__(256) void k_wprep(
    const float* __restrict__ val_w, const float* __restrict__ out_w,
    const float* __restrict__ off_w, const float* __restrict__ aw_w,
    const float* __restrict__ off_b, const float* __restrict__ aw_b,
    const float* __restrict__ ff1_w, const float* __restrict__ ff2_w,
    const float* __restrict__ lat_w,
    __half* __restrict__ valT, __half* __restrict__ outT,
    __half* __restrict__ oaT, float* __restrict__ oab,
    __half* __restrict__ ff1T, __half* __restrict__ ff2T,
    __half* __restrict__ latT)
{
    long long i = (long long)blockIdx.x * 256 + threadIdx.x;
    if (i < 393216) {
        int l = (int)(i >> 16); int w = (int)(i & 65535);
        int n = w >> 8, k = w & 255;
        valT[i] = __float2half_rn(val_w[((long long)l * 256 + k) * 256 + n]);
    } else if (i < 786432) {
        long long j = i - 393216;
        int l = (int)(j >> 16); int w = (int)(j & 65535);
        int n = w >> 8, k = w & 255;
        outT[j] = __float2half_rn(out_w[((long long)l * 256 + k) * 256 + n]);
    } else if (i < 1376256) {
        long long j = i - 786432;
        int l = (int)(j / 98304); int w = (int)(j % 98304);
        int n = w >> 8, k = w & 255;
        float v = 0.f;
        if (n < 192)                  v = off_w[((long long)l * 256 + k) * 192 + n];
        else if (n >= 256 && n < 352) v = aw_w[((long long)l * 256 + k) * 96 + (n - 256)];
        oaT[j] = __float2half_rn(v);
    } else if (i < 1378560) {
        int j = (int)(i - 1376256);
        int l = j / 384, n = j % 384;
        float v = 0.f;
        if (n < 192)                  v = off_b[l * 192 + n];
        else if (n >= 256 && n < 352) v = aw_b[l * 96 + (n - 256)];
        oab[j] = v;
    } else if (i < 2951424) {
        long long j = i - 1378560;
        int l = (int)(j >> 18); int w = (int)(j & 262143);
        int n = w >> 8, k = w & 255;
        ff1T[j] = __float2half_rn(ff1_w[((long long)l * 256 + k) * 1024 + n]);
    } else if (i < 4524288) {
        long long j = i - 2951424;
        int l = (int)(j >> 18); int w = (int)(j & 262143);
        int n = w >> 10, k = w & 1023;
        ff2T[j] = __float2half_rn(ff2_w[((long long)l * 1024 + k) * 256 + n]);
    } else if (i < 4917504) {
        long long j = i - 4524288;
        latT[j] = __float2half_rn(lat_w[j]);
    }
}

// ---------------- host launcher ----------------
extern "C" void kernel_launch(void* const* d_in, const int* in_sizes, int n_in,
                              void* d_out, int out_size)
{
    const float *src0, *src1, *src2, *pos0, *pos1, *pos2;
    if (in_sizes[1] == in_sizes[0]) {
        src0 = (const float*)d_in[0]; pos0 = (const float*)d_in[1];
        src1 = (const float*)d_in[2]; pos1 = (const float*)d_in[3];
        src2 = (const float*)d_in[4]; pos2 = (const float*)d_in[5];
    } else {
        src0 = (const float*)d_in[0]; src1 = (const float*)d_in[1]; src2 = (const float*)d_in[2];
        pos0 = (const float*)d_in[3]; pos1 = (const float*)d_in[4]; pos2 = (const float*)d_in[5];
    }
    const float* mf     = (const float*)d_in[6];
    const float* lev    = (const float*)d_in[7];
    const float* off_w  = (const float*)d_in[8];
    const float* off_b  = (const float*)d_in[9];
    const float* aw_w   = (const float*)d_in[10];
    const float* aw_b   = (const float*)d_in[11];
    const float* val_w  = (const float*)d_in[12];
    const float* val_b  = (const float*)d_in[13];
    const float* out_w  = (const float*)d_in[14];
    const float* out_b  = (const float*)d_in[15];
    const float* ln1_g  = (const float*)d_in[16];
    const float* ln1_b  = (const float*)d_in[17];
    const float* ff1_w  = (const float*)d_in[18];
    const float* ff1_b  = (const float*)d_in[19];
    const float* ff2_w  = (const float*)d_in[20];
    const float* ff2_b  = (const float*)d_in[21];
    const float* ln2_g  = (const float*)d_in[22];
    const float* ln2_b  = (const float*)d_in[23];
    const float* lat_w  = (const float*)d_in[24];
    const float* lat_b  = (const float*)d_in[25];
    const float* outc_w = (const float*)d_in[26];
    const float* outc_b = (const float*)d_in[27];

    float* outp = (float*)d_out;
    float* mask = outp + (size_t)ROWS_TOK * CC;

    cudaFuncSetAttribute(k_mma<0>, cudaFuncAttributeMaxDynamicSharedMemorySize, SMEM_MMA);
    cudaFuncSetAttribute(k_mma<1>, cudaFuncAttributeMaxDynamicSharedMemorySize, SMEM_MMA);
    cudaFuncSetAttribute(k_mma<2>, cudaFuncAttributeMaxDynamicSharedMemorySize, SMEM_MMA);

    static cudaStream_t s_fpn = nullptr, s_val = nullptr;
    static cudaEvent_t evTok[NLAYERS], evW[NLAYERS], evVal[NLAYERS], evFpn, evRoot, evPro0, evProW;
    if (!s_fpn) {
        cudaStreamCreateWithFlags(&s_fpn, cudaStreamNonBlocking);
        cudaStreamCreateWithFlags(&s_val, cudaStreamNonBlocking);
        for (int i = 0; i < NLAYERS; i++) {
            cudaEventCreateWithFlags(&evTok[i], cudaEventDisableTiming);
            cudaEventCreateWithFlags(&evW[i],   cudaEventDisableTiming);
            cudaEventCreateWithFlags(&evVal[i], cudaEventDisableTiming);
        }
        cudaEventCreateWithFlags(&evFpn,  cudaEventDisableTiming);
        cudaEventCreateWithFlags(&evRoot, cudaEventDisableTiming);
        cudaEventCreateWithFlags(&evPro0, cudaEventDisableTiming);
        cudaEventCreateWithFlags(&evProW, cudaEventDisableTiming);
    }
    cudaStream_t s0 = (cudaStream_t)0;

    float *posf, *oab_buf, *tmpb, *osnap, *mtok, *oabp, *zerob;
    __half *outh, *qh, *vh, *acch, *ffh, *xh, *mh;
    __half *valT, *oaT, *outT, *ff1T, *ff2T, *latT, *gU, *gV, *gM;
    cudaGetSymbolAddress((void**)&posf, g_posf);
    cudaGetSymbolAddress((void**)&oab_buf, g_oa);
    cudaGetSymbolAddress((void**)&tmpb, g_tmp);
    cudaGetSymbolAddress((void**)&osnap, g_osnap);
    cudaGetSymbolAddress((void**)&mtok, g_mtok);
    cudaGetSymbolAddress((void**)&outh, g_outh);
    cudaGetSymbolAddress((void**)&qh,   g_qh);
    cudaGetSymbolAddress((void**)&vh,   g_vh);
    cudaGetSymbolAddress((void**)&acch, g_acch);
    cudaGetSymbolAddress((void**)&ffh,  g_ffh);
    cudaGetSymbolAddress((void**)&xh,   g_xh);
    cudaGetSymbolAddress((void**)&mh,   g_mh);
    cudaGetSymbolAddress((void**)&valT, g_valT);
    cudaGetSymbolAddress((void**)&oaT,  g_oaT);
    cudaGetSymbolAddress((void**)&outT, g_outT);
    cudaGetSymbolAddress((void**)&ff1T, g_ff1T);
    cudaGetSymbolAddress((void**)&ff2T, g_ff2T);
    cudaGetSymbolAddress((void**)&latT, g_latT);
    cudaGetSymbolAddress((void**)&oabp, g_oab);
    cudaGetSymbolAddress((void**)&gU,   g_U);
    cudaGetSymbolAddress((void**)&gV,   g_V);
    cudaGetSymbolAddress((void**)&gM,   g_M);
    cudaGetSymbolAddress((void**)&zerob, g_zerob);

    // ---- fork side streams from capture origin FIRST (capture-legal) ----
    cudaEventRecord(evRoot, s0);
    cudaStreamWaitEvent(s_val, evRoot, 0);
    cudaStreamWaitEvent(s_fpn, evRoot, 0);

    // ---- prologue: data prep on s0, weight prep on s_val (concurrent) ----
    k_build<<<ROWS_TOK, 256>>>(src0, src1, src2, pos0, pos1, pos2, lev, outp, outh, posf, qh);
    k_trpix0<<<dim3(512, 8, 4), 256>>>(mf, mtok, mh);
    cudaEventRecord(evPro0, s0);
    k_wprep<<<19209, 256, 0, s_val>>>(val_w, out_w, off_w, aw_w, off_b, aw_b,
                                      ff1_w, ff2_w, lat_w,
                                      valT, outT, oaT, oabp, ff1T, ff2T, latT);
    k_wu<<<1536, 256, 0, s_val>>>(outc_w, gU);
    cudaEventRecord(evProW, s_val);

    const int MT = ROWS_TOK / 128;   // 168
    const int MP = ROWS_PIX / 128;   // 512

    // lat(0) on s_fpn: needs mh (evPro0) + latT (evProW)
    cudaStreamWaitEvent(s_fpn, evPro0, 0);
    cudaStreamWaitEvent(s_fpn, evProW, 0);
    k_mma<2><<<dim3(2, MP, 1), 256, SMEM_MMA, s_fpn>>>(mh, latT, lat_b, xh, 256, 256, 256, 0, 0, 0);

    // s0 needs oaT/oabp; val(0) on s_val needs outh from build
    cudaStreamWaitEvent(s0, evProW, 0);
    cudaStreamWaitEvent(s_val, evPro0, 0);

    for (int i = 0; i < NLAYERS; i++) {
        if (i > 0) cudaStreamWaitEvent(s_val, evTok[i-1], 0);
        k_mma<2><<<dim3(2, MT, 1), 256, SMEM_MMA, s_val>>>(outh, valT + (long long)i*65536, val_b + i*256, vh, 256, 256, 256, 0, 0, 0);
        cudaEventRecord(evVal[i], s_val);

        k_mma<0><<<dim3(3, MT, 1), 256, SMEM_MMA>>>(qh, oaT + (long long)i*98304, oabp + i*384, oab_buf, 256, 256, 384, 0, 0, 0);

        cudaStreamWaitEvent(s0, evVal[i], 0);
        k_sample<<<ROWS_TOK, 256>>>(vh, oab_buf, acch);

        k_mma<0><<<dim3(2, MT, 1), 256, SMEM_MMA>>>(acch, outT + (long long)i*65536, out_b + i*256, tmpb, 256, 256, 256, 0, 0, 0);
        k_ln<0><<<ROWS_TOK, 256>>>(outp, tmpb, ln1_g + i*256, ln1_b + i*256, outp, outh, nullptr, nullptr, nullptr);

        k_mma<1><<<dim3(8, MT, 1), 256, SMEM_MMA>>>(outh, ff1T + (long long)i*262144, ff1_b + i*1024, ffh, 256, 256, 1024, 0, 0, 0);
        k_mma<0><<<dim3(2, MT, 1), 256, SMEM_MMA>>>(ffh,  ff2T + (long long)i*262144, ff2_b + i*256, tmpb, 1024, 1024, 256, 0, 0, 0);

        if (i > 0) cudaStreamWaitEvent(s0, evW[i-1], 0);   // osnap WAR vs wint(i-1)
        k_ln<1><<<ROWS_TOK, 256>>>(outp, tmpb, ln2_g + i*256, ln2_b + i*256, outp, outh, posf, qh, osnap);
        cudaEventRecord(evTok[i], s0);

        // ---- FPN on s_fpn: wint (needs osnap) -> winograd GEMM -> wout -> lat(i+1) ----
        cudaStreamWaitEvent(s_fpn, evTok[i], 0);
        k_wint<<<NTILES, 256, 0, s_fpn>>>(xh, osnap, gV);
        cudaEventRecord(evW[i], s_fpn);
        k_mma<2><<<dim3(2, 128, 16), 256, SMEM_MMA, s_fpn>>>(gV, gU + (long long)i*16*65536, zerob, gM, 256, 256, 256, (long long)ZPL, 65536LL, (long long)ZPL);
        k_wout<<<NTILES, 256, 0, s_fpn>>>(gM, outc_b + i*256, mtok, mh);
        if (i + 1 < NLAYERS)
            k_mma<2><<<dim3(2, MP, 1), 256, SMEM_MMA, s_fpn>>>(mh, latT + (long long)(i+1)*65536, lat_b + (i+1)*256, xh, 256, 256, 256, 0, 0, 0);
    }

    cudaEventRecord(evFpn, s_fpn);
    cudaStreamWaitEvent(s0, evFpn, 0);
    k_trpix1<<<dim3(512, 8, 4), 256>>>(mtok, mask);
}

// round 17
// speedup vs baseline: 1.0641x; 1.0641x over previous
#include <cuda_runtime.h>
#include <cuda_fp16.h>
#include <cstdint>
#include <math.h>

// ---------------- problem constants ----------------
#define CC        256
#define LQQ       5376
#define BTT       4
#define NLAYERS   6
#define NPIX      16384
#define ROWS_TOK  (BTT*LQQ)     // 21504
#define ROWS_PIX  (BTT*NPIX)    // 65536
#define NTILES    16384         // BTT * 64 * 64 winograd tiles
#define ZPL       (NTILES*256)  // elements per winograd z-plane

// ---------------- scratch (device globals) ----------------
__device__ float  g_posf[ROWS_TOK*CC];
__device__ float  g_oa  [ROWS_TOK*384];
__device__ float  g_tmp [ROWS_TOK*CC];
__device__ float  g_osnap[ROWS_TOK*CC];
__device__ float  g_mtok[(long long)ROWS_PIX*CC];
__device__ __half g_outh[ROWS_TOK*CC];
__device__ __half g_qh  [ROWS_TOK*CC];
__device__ __half g_vh  [ROWS_TOK*CC];
__device__ __half g_acch[ROWS_TOK*CC];
__device__ __half g_ffh [ROWS_TOK*1024];
__device__ __half g_xh  [(long long)ROWS_PIX*CC];
__device__ __half g_mh  [(long long)ROWS_PIX*CC];
__device__ __half g_valT[NLAYERS*65536];
__device__ __half g_oaT [NLAYERS*98304];
__device__ __half g_outT[NLAYERS*65536];
__device__ __half g_ff1T[NLAYERS*262144];
__device__ __half g_ff2T[NLAYERS*262144];
__device__ __half g_latT[NLAYERS*65536];
__device__ float  g_oab [NLAYERS*384];
__device__ __half g_U   [(long long)NLAYERS*16*65536];
__device__ __half g_V   [(long long)16*ZPL];
__device__ __half g_M   [(long long)16*ZPL];
__device__ float  g_zerob[256];

// ---------------- helpers ----------------
__device__ __forceinline__ void mma_f16(float* d, const uint32_t* a, const uint32_t* b){
    asm volatile("mma.sync.aligned.m16n8k16.row.col.f32.f16.f16.f32 "
        "{%0,%1,%2,%3}, {%4,%5,%6,%7}, {%8,%9}, {%0,%1,%2,%3};"
        : "+f"(d[0]), "+f"(d[1]), "+f"(d[2]), "+f"(d[3])
        : "r"(a[0]), "r"(a[1]), "r"(a[2]), "r"(a[3]), "r"(b[0]), "r"(b[1]));
}
__device__ __forceinline__ void ldsm4(uint32_t* r, uint32_t addr){
    asm volatile("ldmatrix.sync.aligned.m8n8.x4.shared.b16 {%0,%1,%2,%3}, [%4];"
        : "=r"(r[0]), "=r"(r[1]), "=r"(r[2]), "=r"(r[3]) : "r"(addr));
}
__device__ __forceinline__ uint32_t smem_u32(const void* p){
    uint32_t a; asm("{ .reg .u64 t; cvta.to.shared.u64 t, %1; cvt.u32.u64 %0, t; }" : "=r"(a) : "l"(p)); return a;
}
__device__ __forceinline__ void cpa16(uint32_t dst, const void* src){
    asm volatile("cp.async.cg.shared.global [%0], [%1], 16;\n" :: "r"(dst), "l"(src) : "memory");
}
#define CPA_COMMIT() asm volatile("cp.async.commit_group;" ::: "memory")
#define CPA_WAIT(n)  asm volatile("cp.async.wait_group %0;" :: "n"(n) : "memory")

// ---------------- fp16 mma GEMM: BM=BN=128, BK=32, NSTG=4, single-sync, z-batched ----
// EPI 0: float C = acc+bias
// EPI 1: half  C = relu(acc+bias)
// EPI 2: half  C = acc+bias
// EPI 3: half  C = acc+bias+bilinear_up(up fp32)
#define LDH  40
#define STH  (128*LDH)
#define NSTG 4
#define SMEM_MMA (NSTG*2*STH*2)         // 81920 bytes

__device__ __forceinline__ void issue_tile(
    const __half* __restrict__ A, const __half* __restrict__ B,
    uint32_t smA, uint32_t smB, int kc, long long m0, int n0, int lda, int ldbK, int tid)
{
    const int row = tid >> 1;
    const int s0  = (tid & 1) * 2;
#pragma unroll
    for (int j = 0; j < 2; j++) {
        const int slot = s0 + j;
        cpa16(smA + (uint32_t)(row * LDH + slot * 8) * 2u,
              A + (m0 + row) * (long long)lda + kc * 32 + slot * 8);
        cpa16(smB + (uint32_t)(row * LDH + slot * 8) * 2u,
              B + (long long)(n0 + row) * ldbK + kc * 32 + slot * 8);
    }
}

template<int EPI>
__global__ void __launch_bounds__(256, 2) k_mma(
    const __half* __restrict__ A, const __half* __restrict__ B,
    const float* __restrict__ bias, void* __restrict__ Cv,
    const float* __restrict__ up,
    int K, int lda, int ldc,
    long long zsa, long long zsb, long long zsc)
{
    extern __shared__ __half smh[];
    const uint32_t smbase = smem_u32(smh);

    A += (long long)blockIdx.z * zsa;
    B += (long long)blockIdx.z * zsb;
    const long long czoff = (long long)blockIdx.z * zsc;

    const int tid  = threadIdx.x;
    const int lane = tid & 31;
    const int wid  = tid >> 5;
    const int wm   = wid >> 1;
    const int wn   = wid & 1;
    const int gq   = lane >> 2;
    const int tg   = lane & 3;
    const long long m0 = (long long)blockIdx.y * 128;
    const int n0 = blockIdx.x * 128;
    const int NC = K >> 5;

    const int aoff = (wm * 32 + (lane & 7) + (lane & 8)) * LDH + ((lane & 16) >> 1);
    const int boff = (wn * 64 + (lane & 7) + ((lane & 16) >> 1)) * LDH + (lane & 8);

#pragma unroll
    for (int s = 0; s < NSTG - 1; s++) {
        if (s < NC) {
            issue_tile(A, B, smbase + (uint32_t)(s*2*STH)*2u,
                       smbase + (uint32_t)((s*2+1)*STH)*2u, s, m0, n0, lda, K, tid);
            CPA_COMMIT();
        }
    }

    float acc[2][8][4];
#pragma unroll
    for (int i = 0; i < 2; i++)
#pragma unroll
        for (int j = 0; j < 8; j++)
#pragma unroll
            for (int t = 0; t < 4; t++) acc[i][j][t] = 0.f;

    for (int kc = 0; kc < NC; kc++) {
        const int rem = NC - 1 - kc;
        if (rem >= 2)      CPA_WAIT(2);
        else if (rem == 1) CPA_WAIT(1);
        else               CPA_WAIT(0);
        __syncthreads();

        const int nt = kc + NSTG - 1;
        if (nt < NC) {
            const int wst = nt % NSTG;
            issue_tile(A, B, smbase + (uint32_t)(wst*2*STH)*2u,
                       smbase + (uint32_t)((wst*2+1)*STH)*2u, nt, m0, n0, lda, K, tid);
            CPA_COMMIT();
        }

        const int st = kc % NSTG;
        const uint32_t stA = smbase + (uint32_t)(st * 2 * STH) * 2u;
        const uint32_t stB = stA + (uint32_t)STH * 2u;
#pragma unroll
        for (int ks = 0; ks < 2; ks++) {
            uint32_t afr[2][4], bfr[8][2];
#pragma unroll
            for (int im = 0; im < 2; im++)
                ldsm4(afr[im], stA + (uint32_t)(aoff + im * 16 * LDH + ks * 16) * 2u);
#pragma unroll
            for (int g = 0; g < 4; g++) {
                uint32_t t4[4];
                ldsm4(t4, stB + (uint32_t)(boff + g * 16 * LDH + ks * 16) * 2u);
                bfr[2*g][0] = t4[0]; bfr[2*g][1] = t4[1];
                bfr[2*g+1][0] = t4[2]; bfr[2*g+1][1] = t4[3];
            }
#pragma unroll
            for (int im = 0; im < 2; im++)
#pragma unroll
                for (int in_ = 0; in_ < 8; in_++)
                    mma_f16(acc[im][in_], afr[im], bfr[in_]);
        }
    }

    // ---- epilogue ----
    float* Cf = (float*)Cv;
    __half* Ch = (__half*)Cv;
#pragma unroll
    for (int im = 0; im < 2; im++) {
        const long long rbase = m0 + wm * 32 + im * 16 + gq;
#pragma unroll
        for (int half_ = 0; half_ < 2; half_++) {
            const long long r = rbase + half_ * 8;
            float fx = 0.f, fy = 0.f;
            const float* ub = nullptr;
            int x0 = 0, x1 = 0, y0 = 0, y1 = 0;
            if (EPI == 3) {
                const int bt = (int)(r >> 14);
                const int p  = (int)(r & 16383);
                const int w = p & 127, h = p >> 7;
                float sx = fminf(fmaxf(w * 0.5f - 0.25f, 0.f), 63.f);
                float sy = fminf(fmaxf(h * 0.5f - 0.25f, 0.f), 63.f);
                x0 = (int)sx; y0 = (int)sy;
                x1 = min(x0 + 1, 63); y1 = min(y0 + 1, 63);
                fx = sx - x0; fy = sy - y0;
                ub = up + ((long long)bt * LQQ + 1280) * 256;
            }
#pragma unroll
            for (int in_ = 0; in_ < 8; in_++) {
                const int col = n0 + wn * 64 + in_ * 8 + tg * 2;
                float ox = acc[im][in_][half_ * 2 + 0] + bias[col];
                float oy = acc[im][in_][half_ * 2 + 1] + bias[col + 1];
                if (EPI == 1) { ox = fmaxf(ox, 0.f); oy = fmaxf(oy, 0.f); }
                if (EPI == 3) {
                    const float w00 = (1.f - fx) * (1.f - fy), w01 = fx * (1.f - fy);
                    const float w10 = (1.f - fx) * fy,         w11 = fx * fy;
                    const float* p00 = ub + (y0 * 64 + x0) * 256 + col;
                    const float* p01 = ub + (y0 * 64 + x1) * 256 + col;
                    const float* p10 = ub + (y1 * 64 + x0) * 256 + col;
                    const float* p11 = ub + (y1 * 64 + x1) * 256 + col;
                    ox += w00 * p00[0] + w01 * p01[0] + w10 * p10[0] + w11 * p11[0];
                    oy += w00 * p00[1] + w01 * p01[1] + w10 * p10[1] + w11 * p11[1];
                }
                const long long ci = r * (long long)ldc + col + czoff;
                if (EPI == 0) {
                    *(float2*)(Cf + ci) = make_float2(ox, oy);
                } else {
                    *(__half2*)(Ch + ci) = __floats2half2_rn(ox, oy);
                }
            }
        }
    }
}

// ---------------- winograd F(2x2,3x3) input transform: xh -> V[16][tile][c] ----------
__global__ __launch_bounds__(256) void k_wint(const __half* __restrict__ xh, __half* __restrict__ V)
{
    const int i = blockIdx.x * 256 + threadIdx.x;   // NTILES*256
    const int c    = i & 255;
    const int tile = i >> 8;
    const int tx = tile & 63, ty = (tile >> 6) & 63, bt = tile >> 12;
    const int h0 = 2 * ty - 1, w0 = 2 * tx - 1;

    float d[4][4];
#pragma unroll
    for (int r = 0; r < 4; r++) {
        const int h = h0 + r;
        const bool hok = (unsigned)h < 128u;
#pragma unroll
        for (int s = 0; s < 4; s++) {
            const int w = w0 + s;
            d[r][s] = (hok && (unsigned)w < 128u)
                ? __half2float(xh[((long long)((bt << 14) + (h << 7) + w)) * 256 + c]) : 0.f;
        }
    }
    float t[4][4];
#pragma unroll
    for (int j = 0; j < 4; j++) {
        t[0][j] = d[0][j] - d[2][j];
        t[1][j] = d[1][j] + d[2][j];
        t[2][j] = d[2][j] - d[1][j];
        t[3][j] = d[1][j] - d[3][j];
    }
    const long long base = (long long)tile * 256 + c;
#pragma unroll
    for (int r = 0; r < 4; r++) {
        V[(long long)(r*4+0) * ZPL + base] = __float2half_rn(t[r][0] - t[r][2]);
        V[(long long)(r*4+1) * ZPL + base] = __float2half_rn(t[r][1] + t[r][2]);
        V[(long long)(r*4+2) * ZPL + base] = __float2half_rn(t[r][2] - t[r][1]);
        V[(long long)(r*4+3) * ZPL + base] = __float2half_rn(t[r][1] - t[r][3]);
    }
}

// ---------------- winograd output transform + bias + relu + mask accumulate ----------
__global__ __launch_bounds__(256) void k_wout(const __half* __restrict__ M,
    const float* __restrict__ bias, float* __restrict__ mtok, __half* __restrict__ mh)
{
    const int i = blockIdx.x * 256 + threadIdx.x;
    const int c    = i & 255;
    const int tile = i >> 8;
    const int tx = tile & 63, ty = (tile >> 6) & 63, bt = tile >> 12;

    float m[4][4];
    const long long base = (long long)tile * 256 + c;
#pragma unroll
    for (int z = 0; z < 16; z++)
        m[z >> 2][z & 3] = __half2float(M[(long long)z * ZPL + base]);

    float t[2][4];
#pragma unroll
    for (int j = 0; j < 4; j++) {
        t[0][j] = m[0][j] + m[1][j] + m[2][j];
        t[1][j] = m[1][j] - m[2][j] - m[3][j];
    }
    float y[2][2];
#pragma unroll
    for (int r = 0; r < 2; r++) {
        y[r][0] = t[r][0] + t[r][1] + t[r][2];
        y[r][1] = t[r][1] - t[r][2] - t[r][3];
    }
    const float bb = bias[c];
#pragma unroll
    for (int r = 0; r < 2; r++) {
#pragma unroll
        for (int s = 0; s < 2; s++) {
            const int py = 2 * ty + r, px = 2 * tx + s;
            const long long idx = ((long long)((bt << 14) + (py << 7) + px)) * 256 + c;
            float nv = mtok[idx] + fmaxf(y[r][s] + bb, 0.f);
            mtok[idx] = nv;
            mh[idx] = __float2half_rn(nv);
        }
    }
}

// ---------------- winograd weight transform ----------------
__global__ __launch_bounds__(256) void k_wu(const float* __restrict__ w, __half* __restrict__ U)
{
    const int i = blockIdx.x * 256 + threadIdx.x;   // NLAYERS*65536
    const int ic = i & 255;
    const int oc = (i >> 8) & 255;
    const int l  = i >> 16;
    const float* g = w + (((long long)l * 256 + oc) * 256 + ic) * 9;
    float Gg[4][3];
#pragma unroll
    for (int s = 0; s < 3; s++) {
        Gg[0][s] = g[s];
        Gg[1][s] = 0.5f * (g[s] + g[3 + s] + g[6 + s]);
        Gg[2][s] = 0.5f * (g[s] - g[3 + s] + g[6 + s]);
        Gg[3][s] = g[6 + s];
    }
#pragma unroll
    for (int r = 0; r < 4; r++) {
        const long long lb = ((long long)l * 16 + r * 4) * 65536 + oc * 256 + ic;
        U[lb]          = __float2half_rn(Gg[r][0]);
        U[lb + 65536]  = __float2half_rn(0.5f * (Gg[r][0] + Gg[r][1] + Gg[r][2]));
        U[lb + 131072] = __float2half_rn(0.5f * (Gg[r][0] - Gg[r][1] + Gg[r][2]));
        U[lb + 196608] = __float2half_rn(Gg[r][2]);
    }
}

// ---------------- token build ----------------
__global__ __launch_bounds__(256) void k_build(
    const float* __restrict__ s0, const float* __restrict__ s1, const float* __restrict__ s2,
    const float* __restrict__ p0, const float* __restrict__ p1, const float* __restrict__ p2,
    const float* __restrict__ lev, float* __restrict__ out, __half* __restrict__ outh,
    float* __restrict__ posf, __half* __restrict__ qh)
{
    long long i = (long long)blockIdx.x * 256 + threadIdx.x;
    int c = (int)(i & 255);
    long long r = i >> 8;
    int q  = (int)(r % LQQ);
    int bt = (int)(r / LQQ);
    int l, H, qq;
    if (q < 256)       { l = 0; H = 16; qq = q; }
    else if (q < 1280) { l = 1; H = 32; qq = q - 256; }
    else               { l = 2; H = 64; qq = q - 1280; }
    const float* s = (l == 0) ? s0 : (l == 1 ? s1 : s2);
    const float* p = (l == 0) ? p0 : (l == 1 ? p1 : p2);
    long long src = ((long long)(bt * CC + c)) * H * H + qq;
    float sv = s[src];
    float pv = p[src] + lev[l * CC + c];
    out[i]  = sv;
    outh[i] = __float2half_rn(sv);
    posf[i] = pv;
    qh[i]   = __float2half_rn(sv + pv);
}

// ---------------- deformable sampling ----------------
__global__ __launch_bounds__(256) void k_sample(
    const __half* __restrict__ v, const float* __restrict__ oa, __half* __restrict__ acc)
{
    int bq   = blockIdx.x;
    int h    = threadIdx.x >> 5;
    int lane = threadIdx.x & 31;
    int bt = bq / LQQ, q = bq % LQQ;

    int Hq, qq;
    if (q < 256)       { Hq = 16; qq = q; }
    else if (q < 1280) { Hq = 32; qq = q - 256; }
    else               { Hq = 64; qq = q - 1280; }
    float rx = ((qq % Hq) + 0.5f) / (float)Hq;
    float ry = ((qq / Hq) + 0.5f) / (float)Hq;

    const float* awp = oa + (long long)bq * 384 + 256 + h * 12;
    float a[12];
    float m = -1e30f;
#pragma unroll
    for (int j = 0; j < 12; j++) { a[j] = awp[j]; m = fmaxf(m, a[j]); }
    float s = 0.f;
#pragma unroll
    for (int j = 0; j < 12; j++) { a[j] = __expf(a[j] - m); s += a[j]; }
    float inv = 1.f / s;

    const float* offp = oa + (long long)bq * 384 + h * 24;
    float sum = 0.f;
    const int starts[3] = {0, 256, 1280};
    const int hs[3]     = {16, 32, 64};

#pragma unroll
    for (int l = 0; l < 3; l++) {
        int H = hs[l], W = hs[l];
        const __half* vl = v + ((long long)bt * LQQ + starts[l]) * CC + h * 32 + lane;
#pragma unroll
        for (int p = 0; p < 4; p++) {
            float ox = offp[(l * 4 + p) * 2 + 0];
            float oy = offp[(l * 4 + p) * 2 + 1];
            float x = rx * W + ox - 0.5f;
            float y = ry * H + oy - 0.5f;
            float x0f = floorf(x), y0f = floorf(y);
            int x0 = (int)x0f, y0 = (int)y0f;
            float fx = x - x0f, fy = y - y0f;
            float w00 = (1.f - fx) * (1.f - fy);
            float w01 = fx * (1.f - fy);
            float w10 = (1.f - fx) * fy;
            float w11 = fx * fy;
            float g = 0.f;
            if (y0 >= 0 && y0 < H) {
                if (x0 >= 0 && x0 < W)         g += w00 * __half2float(vl[(long long)(y0 * W + x0) * CC]);
                if (x0 + 1 >= 0 && x0 + 1 < W) g += w01 * __half2float(vl[(long long)(y0 * W + x0 + 1) * CC]);
            }
            if (y0 + 1 >= 0 && y0 + 1 < H) {
                if (x0 >= 0 && x0 < W)         g += w10 * __half2float(vl[(long long)((y0 + 1) * W + x0) * CC]);
                if (x0 + 1 >= 0 && x0 + 1 < W) g += w11 * __half2float(vl[(long long)((y0 + 1) * W + x0 + 1) * CC]);
            }
            sum += (a[l * 4 + p] * inv) * g;
        }
    }
    acc[(long long)bq * CC + h * 32 + lane] = __float2half_rn(sum);
}

// ---------------- layernorm ----------------
template<int QOUT>
__global__ __launch_bounds__(256) void k_ln(
    const float* __restrict__ res, const float* __restrict__ delta,
    const float* __restrict__ g, const float* __restrict__ b,
    float* __restrict__ out, __half* __restrict__ outh,
    const float* __restrict__ posf, __half* __restrict__ qh, float* __restrict__ osnap)
{
    int row = blockIdx.x, c = threadIdx.x;
    long long idx = (long long)row * CC + c;
    float x = res[idx] + delta[idx];
    float s1 = x, s2 = x * x;
#pragma unroll
    for (int o = 16; o; o >>= 1) {
        s1 += __shfl_xor_sync(0xffffffffu, s1, o);
        s2 += __shfl_xor_sync(0xffffffffu, s2, o);
    }
    __shared__ float a1[8], a2[8];
    int wid = c >> 5, ln = c & 31;
    if (ln == 0) { a1[wid] = s1; a2[wid] = s2; }
    __syncthreads();
    float S1 = 0.f, S2 = 0.f;
#pragma unroll
    for (int k = 0; k < 8; k++) { S1 += a1[k]; S2 += a2[k]; }
    float mean = S1 * (1.f / 256.f);
    float var  = S2 * (1.f / 256.f) - mean * mean;
    float r = rsqrtf(var + 1e-5f);
    float y = (x - mean) * r * g[c] + b[c];
    out[idx]  = y;
    outh[idx] = __float2half_rn(y);
    if (QOUT) {
        qh[idx] = __float2half_rn(y + posf[idx]);
        osnap[idx] = y;
    }
}

// ---------------- mask transposes ----------------
__global__ __launch_bounds__(256) void k_trpix0(const float* __restrict__ src,
                                                float* __restrict__ dst, __half* __restrict__ dsth)
{
    __shared__ float t[32][33];
    int tx = threadIdx.x & 31, ty = threadIdx.x >> 5;
    int p0 = blockIdx.x << 5;
    int c0 = blockIdx.y << 5;
    int bt = blockIdx.z;
    int b = bt >> 1, tt = bt & 1;
#pragma unroll
    for (int r = 0; r < 4; r++) {
        int c = c0 + ty + r * 8;
        t[ty + r * 8][tx] = src[(((long long)(b * CC + c)) * 2 + tt) * NPIX + p0 + tx];
    }
    __syncthreads();
#pragma unroll
    for (int r = 0; r < 4; r++) {
        int p = p0 + ty + r * 8;
        float v = t[tx][ty + r * 8];
        long long di = ((long long)bt * NPIX + p) * CC + c0 + tx;
        dst[di]  = v;
        dsth[di] = __float2half_rn(v);
    }
}

__global__ __launch_bounds__(256) void k_trpix1(const float* __restrict__ src, float* __restrict__ dst)
{
    __shared__ float t[32][33];
    int tx = threadIdx.x & 31, ty = threadIdx.x >> 5;
    int p0 = blockIdx.x << 5;
    int c0 = blockIdx.y << 5;
    int bt = blockIdx.z;
    int b = bt >> 1, tt = bt & 1;
#pragma unroll
    for (int r = 0; r < 4; r++) {
        int p = p0 + ty + r * 8;
        t[ty + r * 8][tx] = src[((long long)bt * NPIX + p) * CC + c0 + tx];
    }
    __syncthreads();
#pragma unroll
    for (int r = 0; r < 4; r++) {
        int c = c0 + ty + r * 8;
        dst[(((long long)(b * CC + c)) * 2 + tt) * NPIX + p0 + tx] = t[tx][ty + r * 8];
    }
}

// ---------------- fused weight prep ----------------
__global__ __launch_bounds__(256) void k_wprep(
    const float* __restrict__ val_w, const float* __restrict__ out_w,
    const float* __restrict__ off_w, const float* __restrict__ aw_w,
    const float* __restrict__ off_b, const float* __restrict__ aw_b,
    const float* __restrict__ ff1_w, const float* __restrict__ ff2_w,
    const float* __restrict__ lat_w,
    __half* __restrict__ valT, __half* __restrict__ outT,
    __half* __restrict__ oaT, float* __restrict__ oab,
    __half* __restrict__ ff1T, __half* __restrict__ ff2T,
    __half* __restrict__ latT)
{
    long long i = (long long)blockIdx.x * 256 + threadIdx.x;
    if (i < 393216) {
        int l = (int)(i >> 16); int w = (int)(i & 65535);
        int n = w >> 8, k = w & 255;
        valT[i] = __float2half_rn(val_w[((long long)l * 256 + k) * 256 + n]);
    } else if (i < 786432) {
        long long j = i - 393216;
        int l = (int)(j >> 16); int w = (int)(j & 65535);
        int n = w >> 8, k = w & 255;
        outT[j] = __float2half_rn(out_w[((long long)l * 256 + k) * 256 + n]);
    } else if (i < 1376256) {
        long long j = i - 786432;
        int l = (int)(j / 98304); int w = (int)(j % 98304);
        int n = w >> 8, k = w & 255;
        float v = 0.f;
        if (n < 192)                  v = off_w[((long long)l * 256 + k) * 192 + n];
        else if (n >= 256 && n < 352) v = aw_w[((long long)l * 256 + k) * 96 + (n - 256)];
        oaT[j] = __float2half_rn(v);
    } else if (i < 1378560) {
        int j = (int)(i - 1376256);
        int l = j / 384, n = j % 384;
        float v = 0.f;
        if (n < 192)                  v = off_b[l * 192 + n];
        else if (n >= 256 && n < 352) v = aw_b[l * 96 + (n - 256)];
        oab[j] = v;
    } else if (i < 2951424) {
        long long j = i - 1378560;
        int l = (int)(j >> 18); int w = (int)(j & 262143);
        int n = w >> 8, k = w & 255;
        ff1T[j] = __float2half_rn(ff1_w[((long long)l * 256 + k) * 1024 + n]);
    } else if (i < 4524288) {
        long long j = i - 2951424;
        int l = (int)(j >> 18); int w = (int)(j & 262143);
        int n = w >> 10, k = w & 1023;
        ff2T[j] = __float2half_rn(ff2_w[((long long)l * 1024 + k) * 256 + n]);
    } else if (i < 4917504) {
        long long j = i - 4524288;
        latT[j] = __float2half_rn(lat_w[j]);
    }
}

// ---------------- host launcher ----------------
extern "C" void kernel_launch(void* const* d_in, const int* in_sizes, int n_in,
                              void* d_out, int out_size)
{
    const float *src0, *src1, *src2, *pos0, *pos1, *pos2;
    if (in_sizes[1] == in_sizes[0]) {
        src0 = (const float*)d_in[0]; pos0 = (const float*)d_in[1];
        src1 = (const float*)d_in[2]; pos1 = (const float*)d_in[3];
        src2 = (const float*)d_in[4]; pos2 = (const float*)d_in[5];
    } else {
        src0 = (const float*)d_in[0]; src1 = (const float*)d_in[1]; src2 = (const float*)d_in[2];
        pos0 = (const float*)d_in[3]; pos1 = (const float*)d_in[4]; pos2 = (const float*)d_in[5];
    }
    const float* mf     = (const float*)d_in[6];
    const float* lev    = (const float*)d_in[7];
    const float* off_w  = (const float*)d_in[8];
    const float* off_b  = (const float*)d_in[9];
    const float* aw_w   = (const float*)d_in[10];
    const float* aw_b   = (const float*)d_in[11];
    const float* val_w  = (const float*)d_in[12];
    const float* val_b  = (const float*)d_in[13];
    const float* out_w  = (const float*)d_in[14];
    const float* out_b  = (const float*)d_in[15];
    const float* ln1_g  = (const float*)d_in[16];
    const float* ln1_b  = (const float*)d_in[17];
    const float* ff1_w  = (const float*)d_in[18];
    const float* ff1_b  = (const float*)d_in[19];
    const float* ff2_w  = (const float*)d_in[20];
    const float* ff2_b  = (const float*)d_in[21];
    const float* ln2_g  = (const float*)d_in[22];
    const float* ln2_b  = (const float*)d_in[23];
    const float* lat_w  = (const float*)d_in[24];
    const float* lat_b  = (const float*)d_in[25];
    const float* outc_w = (const float*)d_in[26];
    const float* outc_b = (const float*)d_in[27];

    float* outp = (float*)d_out;
    float* mask = outp + (size_t)ROWS_TOK * CC;

    cudaFuncSetAttribute(k_mma<0>, cudaFuncAttributeMaxDynamicSharedMemorySize, SMEM_MMA);
    cudaFuncSetAttribute(k_mma<1>, cudaFuncAttributeMaxDynamicSharedMemorySize, SMEM_MMA);
    cudaFuncSetAttribute(k_mma<2>, cudaFuncAttributeMaxDynamicSharedMemorySize, SMEM_MMA);
    cudaFuncSetAttribute(k_mma<3>, cudaFuncAttributeMaxDynamicSharedMemorySize, SMEM_MMA);

    static cudaStream_t s_fpn = nullptr, s_val = nullptr;
    static cudaEvent_t evTok[NLAYERS], evLat[NLAYERS], evVal[NLAYERS], evFpn, evRoot, evPro0, evProW;
    if (!s_fpn) {
        cudaStreamCreateWithFlags(&s_fpn, cudaStreamNonBlocking);
        cudaStreamCreateWithFlags(&s_val, cudaStreamNonBlocking);
        for (int i = 0; i < NLAYERS; i++) {
            cudaEventCreateWithFlags(&evTok[i], cudaEventDisableTiming);
            cudaEventCreateWithFlags(&evLat[i], cudaEventDisableTiming);
            cudaEventCreateWithFlags(&evVal[i], cudaEventDisableTiming);
        }
        cudaEventCreateWithFlags(&evFpn,  cudaEventDisableTiming);
        cudaEventCreateWithFlags(&evRoot, cudaEventDisableTiming);
        cudaEventCreateWithFlags(&evPro0, cudaEventDisableTiming);
        cudaEventCreateWithFlags(&evProW, cudaEventDisableTiming);
    }
    cudaStream_t s0 = (cudaStream_t)0;

    float *posf, *oab_buf, *tmpb, *osnap, *mtok, *oabp, *zerob;
    __half *outh, *qh, *vh, *acch, *ffh, *xh, *mh;
    __half *valT, *oaT, *outT, *ff1T, *ff2T, *latT, *gU, *gV, *gM;
    cudaGetSymbolAddress((void**)&posf, g_posf);
    cudaGetSymbolAddress((void**)&oab_buf, g_oa);
    cudaGetSymbolAddress((void**)&tmpb, g_tmp);
    cudaGetSymbolAddress((void**)&osnap, g_osnap);
    cudaGetSymbolAddress((void**)&mtok, g_mtok);
    cudaGetSymbolAddress((void**)&outh, g_outh);
    cudaGetSymbolAddress((void**)&qh,   g_qh);
    cudaGetSymbolAddress((void**)&vh,   g_vh);
    cudaGetSymbolAddress((void**)&acch, g_acch);
    cudaGetSymbolAddress((void**)&ffh,  g_ffh);
    cudaGetSymbolAddress((void**)&xh,   g_xh);
    cudaGetSymbolAddress((void**)&mh,   g_mh);
    cudaGetSymbolAddress((void**)&valT, g_valT);
    cudaGetSymbolAddress((void**)&oaT,  g_oaT);
    cudaGetSymbolAddress((void**)&outT, g_outT);
    cudaGetSymbolAddress((void**)&ff1T, g_ff1T);
    cudaGetSymbolAddress((void**)&ff2T, g_ff2T);
    cudaGetSymbolAddress((void**)&latT, g_latT);
    cudaGetSymbolAddress((void**)&oabp, g_oab);
    cudaGetSymbolAddress((void**)&gU,   g_U);
    cudaGetSymbolAddress((void**)&gV,   g_V);
    cudaGetSymbolAddress((void**)&gM,   g_M);
    cudaGetSymbolAddress((void**)&zerob, g_zerob);

    // ---- fork side streams from capture origin FIRST ----
    cudaEventRecord(evRoot, s0);
    cudaStreamWaitEvent(s_val, evRoot, 0);
    cudaStreamWaitEvent(s_fpn, evRoot, 0);

    // ---- prologue: data prep on s0, weight prep on s_val (concurrent) ----
    k_build<<<ROWS_TOK, 256>>>(src0, src1, src2, pos0, pos1, pos2, lev, outp, outh, posf, qh);
    k_trpix0<<<dim3(512, 8, 4), 256>>>(mf, mtok, mh);
    cudaEventRecord(evPro0, s0);
    k_wprep<<<19209, 256, 0, s_val>>>(val_w, out_w, off_w, aw_w, off_b, aw_b,
                                      ff1_w, ff2_w, lat_w,
                                      valT, outT, oaT, oabp, ff1T, ff2T, latT);
    k_wu<<<1536, 256, 0, s_val>>>(outc_w, gU);
    cudaEventRecord(evProW, s_val);

    const int MT = ROWS_TOK / 128;   // 168
    const int MP = ROWS_PIX / 128;   // 512

    // cross-deps for layer 0
    cudaStreamWaitEvent(s0, evProW, 0);     // oa(0) needs oaT
    cudaStreamWaitEvent(s_val, evPro0, 0);  // val(0) needs outh
    cudaStreamWaitEvent(s_fpn, evPro0, 0);  // lat(0) needs mh
    cudaStreamWaitEvent(s_fpn, evProW, 0);  // lat(0) needs latT

    for (int i = 0; i < NLAYERS; i++) {
        if (i > 0) cudaStreamWaitEvent(s_val, evTok[i-1], 0);
        k_mma<2><<<dim3(2, MT, 1), 256, SMEM_MMA, s_val>>>(outh, valT + (long long)i*65536, val_b + i*256, vh, nullptr, 256, 256, 256, 0, 0, 0);
        cudaEventRecord(evVal[i], s_val);

        k_mma<0><<<dim3(3, MT, 1), 256, SMEM_MMA>>>(qh, oaT + (long long)i*98304, oabp + i*384, oab_buf, nullptr, 256, 256, 384, 0, 0, 0);

        cudaStreamWaitEvent(s0, evVal[i], 0);
        k_sample<<<ROWS_TOK, 256>>>(vh, oab_buf, acch);

        k_mma<0><<<dim3(2, MT, 1), 256, SMEM_MMA>>>(acch, outT + (long long)i*65536, out_b + i*256, tmpb, nullptr, 256, 256, 256, 0, 0, 0);
        k_ln<0><<<ROWS_TOK, 256>>>(outp, tmpb, ln1_g + i*256, ln1_b + i*256, outp, outh, nullptr, nullptr, nullptr);

        k_mma<1><<<dim3(8, MT, 1), 256, SMEM_MMA>>>(outh, ff1T + (long long)i*262144, ff1_b + i*1024, ffh, nullptr, 256, 256, 1024, 0, 0, 0);
        k_mma<0><<<dim3(2, MT, 1), 256, SMEM_MMA>>>(ffh,  ff2T + (long long)i*262144, ff2_b + i*256, tmpb, nullptr, 1024, 1024, 256, 0, 0, 0);

        if (i > 0) cudaStreamWaitEvent(s0, evLat[i-1], 0);   // osnap WAR vs lat(i-1)
        k_ln<1><<<ROWS_TOK, 256>>>(outp, tmpb, ln2_g + i*256, ln2_b + i*256, outp, outh, posf, qh, osnap);
        cudaEventRecord(evTok[i], s0);

        // ---- FPN on s_fpn: lat (reads osnap) -> wint -> winograd GEMM -> wout ----
        cudaStreamWaitEvent(s_fpn, evTok[i], 0);
        k_mma<3><<<dim3(2, MP, 1), 256, SMEM_MMA, s_fpn>>>(mh, latT + (long long)i*65536, lat_b + i*256, xh, osnap, 256, 256, 256, 0, 0, 0);
        cudaEventRecord(evLat[i], s_fpn);
        k_wint<<<NTILES, 256, 0, s_fpn>>>(xh, gV);
        k_mma<2><<<dim3(2, 128, 16), 256, SMEM_MMA, s_fpn>>>(gV, gU + (long long)i*16*65536, zerob, gM, nullptr, 256, 256, 256, (long long)ZPL, 65536LL, (long long)ZPL);
        k_wout<<<NTILES, 256, 0, s_fpn>>>(gM, outc_b + i*256, mtok, mh);
    }

    cudaEventRecord(evFpn, s_fpn);
    cudaStreamWaitEvent(s0, evFpn, 0);
    k_trpix1<<<dim3(512, 8, 4), 256>>>(mtok, mask);
}